// round 15
// baseline (speedup 1.0000x reference)
#include <cuda_runtime.h>
#include <cstdint>

// Batched tiny-GCN, B=1e6, V=9, F_IN=5, F_HID=3. HBM stream (~508 MB), at ~96% of
// the measured chip streaming ceiling (~6.6-6.9 TB/s).
// R14: SPB=64 divides 1e6 exactly -> NO ragged tail (removes the uncoalesced
// serial epilogue from the critical path). 3-stage ring of 32.2KB tiles,
// 2 consumer warps + 1 producer warp, 2 independent blocks/SM.

#define V        9
#define FIN      5
#define FH       3
#define TPB      96                         // warps 0-1: consumers (64 lanes), warp 2: producer
#define SPB      64                         // samples per stage; 1e6 / 64 = 15625 exact
#define NSTAGE   3
#define A_PER    (V*V)                      // 81
#define H_PER    (V*FIN)                    // 45
#define A_BYTES  (SPB*A_PER*4)              // 20736
#define H_BYTES  (SPB*H_PER*4)              // 11520
#define STAGE_BYTES (A_BYTES+H_BYTES)       // 32256
#define BAR_BYTES   (NSTAGE*16)
#define SMEM_BYTES  (NSTAGE*STAGE_BYTES + BAR_BYTES)   // 96816 -> 2 blocks/SM

__device__ __forceinline__ void mbar_init(uint32_t mbar, uint32_t cnt) {
    asm volatile("mbarrier.init.shared.b64 [%0], %1;" :: "r"(mbar), "r"(cnt) : "memory");
}
__device__ __forceinline__ void mbar_expect_tx(uint32_t mbar, uint32_t tx) {
    asm volatile("mbarrier.arrive.expect_tx.shared.b64 _, [%0], %1;" :: "r"(mbar), "r"(tx) : "memory");
}
__device__ __forceinline__ void mbar_arrive(uint32_t mbar) {
    asm volatile("mbarrier.arrive.shared.b64 _, [%0];" :: "r"(mbar) : "memory");
}
__device__ __forceinline__ void mbar_wait(uint32_t mbar, uint32_t phase) {
    asm volatile(
        "{\n\t.reg .pred P;\n\t"
        "W_%=:\n\t"
        "mbarrier.try_wait.parity.acquire.cta.shared::cta.b64 P, [%0], %1, 0x989680;\n\t"
        "@!P bra W_%=;\n\t}"
        :: "r"(mbar), "r"(phase) : "memory");
}
__device__ __forceinline__ void mbar_wait_relaxed(uint32_t mbar, uint32_t phase) {
    asm volatile(
        "{\n\t.reg .pred P;\n\t"
        "W_%=:\n\t"
        "mbarrier.try_wait.parity.relaxed.cta.shared::cta.b64 P, [%0], %1, 0x989680;\n\t"
        "@!P bra W_%=;\n\t}"
        :: "r"(mbar), "r"(phase) : "memory");
}
__device__ __forceinline__ void bulk_g2s(uint32_t dst, const void* src, uint32_t bytes, uint32_t mbar) {
    asm volatile("cp.async.bulk.shared::cta.global.mbarrier::complete_tx::bytes [%0], [%1], %2, [%3];"
                 :: "r"(dst), "l"(src), "r"(bytes), "r"(mbar) : "memory");
}

struct Params { float W[FIN][FH]; float fw0, fw1, fw2, fb; };

__device__ __forceinline__ Params load_params(const float* __restrict__ gW,
                                              const float* __restrict__ gFw,
                                              const float* __restrict__ gFb)
{
    Params p;
    #pragma unroll
    for (int f = 0; f < FIN; f++)
        #pragma unroll
        for (int c = 0; c < FH; c++)
            p.W[f][c] = __ldg(gW + f*FH + c);
    p.fw0 = __ldg(gFw + 0); p.fw1 = __ldg(gFw + 1); p.fw2 = __ldg(gFw + 2);
    p.fb  = __ldg(gFb);
    return p;
}

__device__ __forceinline__ float gcn_sample(const float* __restrict__ a,
                                            const float* __restrict__ h,
                                            const Params& p)
{
    // deg_j = 1 + colsum_j(A); dinv = rsqrt
    float dinv[V];
    #pragma unroll
    for (int j = 0; j < V; j++) {
        float d = 1.0f;
        #pragma unroll
        for (int i = 0; i < V; i++) d += a[i*V + j];
        dinv[j] = rsqrtf(d);
    }
    // t[j][c] = dinv_j * (h0 W)[j][c]
    float tj[V][FH];
    #pragma unroll
    for (int j = 0; j < V; j++) {
        #pragma unroll
        for (int c = 0; c < FH; c++) {
            float s = 0.0f;
            #pragma unroll
            for (int f = 0; f < FIN; f++)
                s = fmaf(h[j*FIN + f], p.W[f][c], s);
            tj[j][c] = dinv[j] * s;
        }
    }
    // pooled relu(dinv_i * (t[i] + sum_j A[i][j] t[j]))
    float acc0 = 0.f, acc1 = 0.f, acc2 = 0.f;
    #pragma unroll
    for (int i = 0; i < V; i++) {
        float s0 = tj[i][0], s1 = tj[i][1], s2 = tj[i][2];
        #pragma unroll
        for (int j = 0; j < V; j++) {
            float aij = a[i*V + j];
            s0 = fmaf(aij, tj[j][0], s0);
            s1 = fmaf(aij, tj[j][1], s1);
            s2 = fmaf(aij, tj[j][2], s2);
        }
        float di = dinv[i];
        acc0 += fmaxf(di*s0, 0.0f);
        acc1 += fmaxf(di*s1, 0.0f);
        acc2 += fmaxf(di*s2, 0.0f);
    }
    return fmaf(acc0, p.fw0, fmaf(acc1, p.fw1, fmaf(acc2, p.fw2, p.fb)));
}

__global__ __launch_bounds__(TPB, 2) void gcn_kernel(
    const float* __restrict__ gA,
    const float* __restrict__ gH,
    const float* __restrict__ gW,
    const float* __restrict__ gFw,
    const float* __restrict__ gFb,
    float* __restrict__ out,
    int B)
{
    extern __shared__ __align__(16) unsigned char smem[];
    const uint32_t smemBase = (uint32_t)__cvta_generic_to_shared(smem);
    const uint32_t barBase  = smemBase + NSTAGE * STAGE_BYTES;
    // full[s] at barBase + s*16, empty[s] at barBase + s*16 + 8

    const int tid = threadIdx.x;
    const int wid = tid >> 5;

    if (tid == 0) {
        #pragma unroll
        for (int s = 0; s < NSTAGE; s++) {
            mbar_init(barBase + s*16,     1);    // full: producer expect_tx
            mbar_init(barBase + s*16 + 8, SPB);  // empty: 64 consumer arrivals
        }
    }
    __syncthreads();

    const int nt     = B / SPB;          // 15625 tiles, no remainder
    const int stride = gridDim.x;

    if (wid == 2) {
        // ---------------- producer warp (lane 0) ----------------
        if ((tid & 31) == 0) {
            int s = 0; uint32_t ph = 1;  // first empty-wait passes immediately
            for (int t = blockIdx.x; t < nt; t += stride) {
                mbar_wait_relaxed(barBase + s*16 + 8, ph);
                mbar_expect_tx(barBase + s*16, STAGE_BYTES);
                const uint32_t dst = smemBase + s * STAGE_BYTES;
                bulk_g2s(dst,           gA + (size_t)t * (SPB*A_PER), A_BYTES, barBase + s*16);
                bulk_g2s(dst + A_BYTES, gH + (size_t)t * (SPB*H_PER), H_BYTES, barBase + s*16);
                if (++s == NSTAGE) { s = 0; ph ^= 1; }
            }
        }
    } else {
        // ---------------- consumer warps 0-1: one sample per lane ----------------
        const Params p = load_params(gW, gFw, gFb);
        int s = 0; uint32_t ph = 0;
        for (int t = blockIdx.x; t < nt; t += stride) {
            mbar_wait(barBase + s*16, ph);
            const float* base = reinterpret_cast<const float*>(smem + s * STAGE_BYTES);
            const float* a = base + tid * A_PER;             // stride 81 (odd) -> conflict-free
            const float* h = base + SPB*A_PER + tid * H_PER; // stride 45 (odd) -> conflict-free
            out[(size_t)t * SPB + tid] = gcn_sample(a, h, p);
            mbar_arrive(barBase + s*16 + 8);
            if (++s == NSTAGE) { s = 0; ph ^= 1; }
        }
    }
}

extern "C" void kernel_launch(void* const* d_in, const int* in_sizes, int n_in,
                              void* d_out, int out_size)
{
    const float* A   = (const float*)d_in[0];
    const float* h0  = (const float*)d_in[1];
    const float* W   = (const float*)d_in[2];
    const float* fcw = (const float*)d_in[3];
    const float* fcb = (const float*)d_in[4];
    float* out = (float*)d_out;

    cudaFuncSetAttribute(gcn_kernel, cudaFuncAttributeMaxDynamicSharedMemorySize, SMEM_BYTES);

    const int B = in_sizes[0] / A_PER;    // 1,000,000
    const int grid = 148 * 2;             // 2 blocks/SM, grid-strided tiles
    gcn_kernel<<<grid, TPB, SMEM_BYTES>>>(A, h0, W, fcw, fcb, out, B);
}

// round 16
// speedup vs baseline: 1.0352x; 1.0352x over previous
#include <cuda_runtime.h>
#include <cstdint>

// Batched tiny-GCN, B=1e6, V=9, F_IN=5, F_HID=3. HBM stream (~508 MB).
// R15: R13 structure (warp-specialized producer, 2-stage ring, 2 blocks/SM)
// with SPB=100 -> 10,000 exact tiles, NO ragged tail, bigger bulk copies.
// 4 consumer warps (100 active lanes) + 1 producer warp.

#define V        9
#define FIN      5
#define FH       3
#define TPB      160                        // warps 0-3: consumers (100 of 128 lanes), warp 4: producer
#define SPB      100                        // samples per stage; 1e6 / 100 = 10000 exact
#define NSTAGE   2
#define A_PER    (V*V)                      // 81
#define H_PER    (V*FIN)                    // 45
#define A_BYTES  (SPB*A_PER*4)              // 32400
#define H_BYTES  (SPB*H_PER*4)              // 18000
#define STAGE_BYTES (A_BYTES+H_BYTES)       // 50400
#define BAR_BYTES   (NSTAGE*16)
#define SMEM_BYTES  (NSTAGE*STAGE_BYTES + BAR_BYTES)   // 100832 -> 2 blocks/SM

__device__ __forceinline__ void mbar_init(uint32_t mbar, uint32_t cnt) {
    asm volatile("mbarrier.init.shared.b64 [%0], %1;" :: "r"(mbar), "r"(cnt) : "memory");
}
__device__ __forceinline__ void mbar_expect_tx(uint32_t mbar, uint32_t tx) {
    asm volatile("mbarrier.arrive.expect_tx.shared.b64 _, [%0], %1;" :: "r"(mbar), "r"(tx) : "memory");
}
__device__ __forceinline__ void mbar_arrive(uint32_t mbar) {
    asm volatile("mbarrier.arrive.shared.b64 _, [%0];" :: "r"(mbar) : "memory");
}
__device__ __forceinline__ void mbar_wait(uint32_t mbar, uint32_t phase) {
    asm volatile(
        "{\n\t.reg .pred P;\n\t"
        "W_%=:\n\t"
        "mbarrier.try_wait.parity.acquire.cta.shared::cta.b64 P, [%0], %1, 0x989680;\n\t"
        "@!P bra W_%=;\n\t}"
        :: "r"(mbar), "r"(phase) : "memory");
}
__device__ __forceinline__ void mbar_wait_relaxed(uint32_t mbar, uint32_t phase) {
    asm volatile(
        "{\n\t.reg .pred P;\n\t"
        "W_%=:\n\t"
        "mbarrier.try_wait.parity.relaxed.cta.shared::cta.b64 P, [%0], %1, 0x989680;\n\t"
        "@!P bra W_%=;\n\t}"
        :: "r"(mbar), "r"(phase) : "memory");
}
__device__ __forceinline__ void bulk_g2s(uint32_t dst, const void* src, uint32_t bytes, uint32_t mbar) {
    asm volatile("cp.async.bulk.shared::cta.global.mbarrier::complete_tx::bytes [%0], [%1], %2, [%3];"
                 :: "r"(dst), "l"(src), "r"(bytes), "r"(mbar) : "memory");
}

struct Params { float W[FIN][FH]; float fw0, fw1, fw2, fb; };

__device__ __forceinline__ Params load_params(const float* __restrict__ gW,
                                              const float* __restrict__ gFw,
                                              const float* __restrict__ gFb)
{
    Params p;
    #pragma unroll
    for (int f = 0; f < FIN; f++)
        #pragma unroll
        for (int c = 0; c < FH; c++)
            p.W[f][c] = __ldg(gW + f*FH + c);
    p.fw0 = __ldg(gFw + 0); p.fw1 = __ldg(gFw + 1); p.fw2 = __ldg(gFw + 2);
    p.fb  = __ldg(gFb);
    return p;
}

__device__ __forceinline__ float gcn_sample(const float* __restrict__ a,
                                            const float* __restrict__ h,
                                            const Params& p)
{
    // deg_j = 1 + colsum_j(A); dinv = rsqrt
    float dinv[V];
    #pragma unroll
    for (int j = 0; j < V; j++) {
        float d = 1.0f;
        #pragma unroll
        for (int i = 0; i < V; i++) d += a[i*V + j];
        dinv[j] = rsqrtf(d);
    }
    // t[j][c] = dinv_j * (h0 W)[j][c]
    float tj[V][FH];
    #pragma unroll
    for (int j = 0; j < V; j++) {
        #pragma unroll
        for (int c = 0; c < FH; c++) {
            float s = 0.0f;
            #pragma unroll
            for (int f = 0; f < FIN; f++)
                s = fmaf(h[j*FIN + f], p.W[f][c], s);
            tj[j][c] = dinv[j] * s;
        }
    }
    // pooled relu(dinv_i * (t[i] + sum_j A[i][j] t[j]))
    float acc0 = 0.f, acc1 = 0.f, acc2 = 0.f;
    #pragma unroll
    for (int i = 0; i < V; i++) {
        float s0 = tj[i][0], s1 = tj[i][1], s2 = tj[i][2];
        #pragma unroll
        for (int j = 0; j < V; j++) {
            float aij = a[i*V + j];
            s0 = fmaf(aij, tj[j][0], s0);
            s1 = fmaf(aij, tj[j][1], s1);
            s2 = fmaf(aij, tj[j][2], s2);
        }
        float di = dinv[i];
        acc0 += fmaxf(di*s0, 0.0f);
        acc1 += fmaxf(di*s1, 0.0f);
        acc2 += fmaxf(di*s2, 0.0f);
    }
    return fmaf(acc0, p.fw0, fmaf(acc1, p.fw1, fmaf(acc2, p.fw2, p.fb)));
}

__global__ __launch_bounds__(TPB, 2) void gcn_kernel(
    const float* __restrict__ gA,
    const float* __restrict__ gH,
    const float* __restrict__ gW,
    const float* __restrict__ gFw,
    const float* __restrict__ gFb,
    float* __restrict__ out,
    int B)
{
    extern __shared__ __align__(16) unsigned char smem[];
    const uint32_t smemBase = (uint32_t)__cvta_generic_to_shared(smem);
    const uint32_t barBase  = smemBase + NSTAGE * STAGE_BYTES;
    // full[s] at barBase + s*16, empty[s] at barBase + s*16 + 8

    const int tid = threadIdx.x;
    const int wid = tid >> 5;

    if (tid == 0) {
        #pragma unroll
        for (int s = 0; s < NSTAGE; s++) {
            mbar_init(barBase + s*16,     1);    // full: producer expect_tx
            mbar_init(barBase + s*16 + 8, SPB);  // empty: 100 consumer arrivals
        }
    }
    __syncthreads();

    const int nt     = B / SPB;          // 10000 tiles, no remainder
    const int stride = gridDim.x;

    if (wid == 4) {
        // ---------------- producer warp (lane 0) ----------------
        if ((tid & 31) == 0) {
            int s = 0; uint32_t ph = 1;  // first empty-wait passes immediately
            for (int t = blockIdx.x; t < nt; t += stride) {
                mbar_wait_relaxed(barBase + s*16 + 8, ph);
                mbar_expect_tx(barBase + s*16, STAGE_BYTES);
                const uint32_t dst = smemBase + s * STAGE_BYTES;
                bulk_g2s(dst,           gA + (size_t)t * (SPB*A_PER), A_BYTES, barBase + s*16);
                bulk_g2s(dst + A_BYTES, gH + (size_t)t * (SPB*H_PER), H_BYTES, barBase + s*16);
                if (++s == NSTAGE) { s = 0; ph ^= 1; }
            }
        }
    } else if (tid < SPB) {
        // ---------------- consumer lanes 0-99: one sample per lane ----------------
        const Params p = load_params(gW, gFw, gFb);
        int s = 0; uint32_t ph = 0;
        for (int t = blockIdx.x; t < nt; t += stride) {
            mbar_wait(barBase + s*16, ph);
            const float* base = reinterpret_cast<const float*>(smem + s * STAGE_BYTES);
            const float* a = base + tid * A_PER;             // stride 81 (odd) -> conflict-free
            const float* h = base + SPB*A_PER + tid * H_PER; // stride 45 (odd) -> conflict-free
            out[(size_t)t * SPB + tid] = gcn_sample(a, h, p);
            mbar_arrive(barBase + s*16 + 8);
            if (++s == NSTAGE) { s = 0; ph ^= 1; }
        }
    }
}

extern "C" void kernel_launch(void* const* d_in, const int* in_sizes, int n_in,
                              void* d_out, int out_size)
{
    const float* A   = (const float*)d_in[0];
    const float* h0  = (const float*)d_in[1];
    const float* W   = (const float*)d_in[2];
    const float* fcw = (const float*)d_in[3];
    const float* fcb = (const float*)d_in[4];
    float* out = (float*)d_out;

    cudaFuncSetAttribute(gcn_kernel, cudaFuncAttributeMaxDynamicSharedMemorySize, SMEM_BYTES);

    const int B = in_sizes[0] / A_PER;    // 1,000,000
    const int grid = 148 * 2;             // 2 blocks/SM, grid-strided tiles
    gcn_kernel<<<grid, TPB, SMEM_BYTES>>>(A, h0, W, fcw, fcb, out, B);
}

// round 17
// speedup vs baseline: 1.0560x; 1.0200x over previous
#include <cuda_runtime.h>
#include <cstdint>

// Batched tiny-GCN, B=1e6, V=9, F_IN=5, F_HID=3. HBM stream (~508 MB).
// R16 = R13 (best: producer warp + 2-stage x 96-sample ring, 2 blocks/SM)
//  + L2 evict-first cache hints on the read-once bulk copies
//  + tail integrated as a partial last tile (no serial GMEM epilogue).

#define V        9
#define FIN      5
#define FH       3
#define TPB      128                        // warps 0-2: consumers (96 lanes), warp 3: producer
#define SPB      96                         // samples per stage
#define NSTAGE   2
#define A_PER    (V*V)                      // 81
#define H_PER    (V*FIN)                    // 45
#define A_BYTES  (SPB*A_PER*4)              // 31104
#define H_BYTES  (SPB*H_PER*4)              // 17280
#define STAGE_BYTES (A_BYTES+H_BYTES)       // 48384
#define BAR_BYTES   (NSTAGE*16)
#define SMEM_BYTES  (NSTAGE*STAGE_BYTES + BAR_BYTES)   // 96800 -> 2 blocks/SM

__device__ __forceinline__ void mbar_init(uint32_t mbar, uint32_t cnt) {
    asm volatile("mbarrier.init.shared.b64 [%0], %1;" :: "r"(mbar), "r"(cnt) : "memory");
}
__device__ __forceinline__ void mbar_expect_tx(uint32_t mbar, uint32_t tx) {
    asm volatile("mbarrier.arrive.expect_tx.shared.b64 _, [%0], %1;" :: "r"(mbar), "r"(tx) : "memory");
}
__device__ __forceinline__ void mbar_arrive(uint32_t mbar) {
    asm volatile("mbarrier.arrive.shared.b64 _, [%0];" :: "r"(mbar) : "memory");
}
__device__ __forceinline__ void mbar_wait(uint32_t mbar, uint32_t phase) {
    asm volatile(
        "{\n\t.reg .pred P;\n\t"
        "W_%=:\n\t"
        "mbarrier.try_wait.parity.acquire.cta.shared::cta.b64 P, [%0], %1, 0x989680;\n\t"
        "@!P bra W_%=;\n\t}"
        :: "r"(mbar), "r"(phase) : "memory");
}
__device__ __forceinline__ void mbar_wait_relaxed(uint32_t mbar, uint32_t phase) {
    asm volatile(
        "{\n\t.reg .pred P;\n\t"
        "W_%=:\n\t"
        "mbarrier.try_wait.parity.relaxed.cta.shared::cta.b64 P, [%0], %1, 0x989680;\n\t"
        "@!P bra W_%=;\n\t}"
        :: "r"(mbar), "r"(phase) : "memory");
}
// Bulk copy with L2 evict-first policy (read-once stream: free L2 ways immediately)
__device__ __forceinline__ void bulk_g2s_ef(uint32_t dst, const void* src, uint32_t bytes,
                                            uint32_t mbar, uint64_t pol) {
    asm volatile("cp.async.bulk.shared::cta.global.mbarrier::complete_tx::bytes.L2::cache_hint"
                 " [%0], [%1], %2, [%3], %4;"
                 :: "r"(dst), "l"(src), "r"(bytes), "r"(mbar), "l"(pol) : "memory");
}

struct Params { float W[FIN][FH]; float fw0, fw1, fw2, fb; };

__device__ __forceinline__ Params load_params(const float* __restrict__ gW,
                                              const float* __restrict__ gFw,
                                              const float* __restrict__ gFb)
{
    Params p;
    #pragma unroll
    for (int f = 0; f < FIN; f++)
        #pragma unroll
        for (int c = 0; c < FH; c++)
            p.W[f][c] = __ldg(gW + f*FH + c);
    p.fw0 = __ldg(gFw + 0); p.fw1 = __ldg(gFw + 1); p.fw2 = __ldg(gFw + 2);
    p.fb  = __ldg(gFb);
    return p;
}

__device__ __forceinline__ float gcn_sample(const float* __restrict__ a,
                                            const float* __restrict__ h,
                                            const Params& p)
{
    // deg_j = 1 + colsum_j(A); dinv = rsqrt
    float dinv[V];
    #pragma unroll
    for (int j = 0; j < V; j++) {
        float d = 1.0f;
        #pragma unroll
        for (int i = 0; i < V; i++) d += a[i*V + j];
        dinv[j] = rsqrtf(d);
    }
    // t[j][c] = dinv_j * (h0 W)[j][c]
    float tj[V][FH];
    #pragma unroll
    for (int j = 0; j < V; j++) {
        #pragma unroll
        for (int c = 0; c < FH; c++) {
            float s = 0.0f;
            #pragma unroll
            for (int f = 0; f < FIN; f++)
                s = fmaf(h[j*FIN + f], p.W[f][c], s);
            tj[j][c] = dinv[j] * s;
        }
    }
    // pooled relu(dinv_i * (t[i] + sum_j A[i][j] t[j]))
    float acc0 = 0.f, acc1 = 0.f, acc2 = 0.f;
    #pragma unroll
    for (int i = 0; i < V; i++) {
        float s0 = tj[i][0], s1 = tj[i][1], s2 = tj[i][2];
        #pragma unroll
        for (int j = 0; j < V; j++) {
            float aij = a[i*V + j];
            s0 = fmaf(aij, tj[j][0], s0);
            s1 = fmaf(aij, tj[j][1], s1);
            s2 = fmaf(aij, tj[j][2], s2);
        }
        float di = dinv[i];
        acc0 += fmaxf(di*s0, 0.0f);
        acc1 += fmaxf(di*s1, 0.0f);
        acc2 += fmaxf(di*s2, 0.0f);
    }
    return fmaf(acc0, p.fw0, fmaf(acc1, p.fw1, fmaf(acc2, p.fw2, p.fb)));
}

__global__ __launch_bounds__(TPB, 2) void gcn_kernel(
    const float* __restrict__ gA,
    const float* __restrict__ gH,
    const float* __restrict__ gW,
    const float* __restrict__ gFw,
    const float* __restrict__ gFb,
    float* __restrict__ out,
    int B)
{
    extern __shared__ __align__(16) unsigned char smem[];
    const uint32_t smemBase = (uint32_t)__cvta_generic_to_shared(smem);
    const uint32_t barBase  = smemBase + NSTAGE * STAGE_BYTES;
    // full[s] at barBase + s*16, empty[s] at barBase + s*16 + 8

    const int tid = threadIdx.x;
    const int wid = tid >> 5;

    if (tid == 0) {
        #pragma unroll
        for (int s = 0; s < NSTAGE; s++) {
            mbar_init(barBase + s*16,     1);    // full: producer expect_tx
            mbar_init(barBase + s*16 + 8, SPB);  // empty: 96 consumer arrivals
        }
    }
    __syncthreads();

    const int nt     = (B + SPB - 1) / SPB;   // 10417 tiles, last one partial (64 samples)
    const int stride = gridDim.x;

    if (wid == 3) {
        // ---------------- producer warp (lane 0) ----------------
        if ((tid & 31) == 0) {
            uint64_t pol;
            asm volatile("createpolicy.fractional.L2::evict_first.b64 %0, 1.0;" : "=l"(pol));
            int s = 0; uint32_t ph = 1;  // first empty-wait passes immediately
            for (int t = blockIdx.x; t < nt; t += stride) {
                const int n = min(SPB, B - t * SPB);          // partial last tile
                const uint32_t ab = (uint32_t)n * (A_PER * 4);
                const uint32_t hb = (uint32_t)n * (H_PER * 4);
                mbar_wait_relaxed(barBase + s*16 + 8, ph);
                mbar_expect_tx(barBase + s*16, ab + hb);
                const uint32_t dst = smemBase + s * STAGE_BYTES;
                bulk_g2s_ef(dst,           gA + (size_t)t * (SPB*A_PER), ab, barBase + s*16, pol);
                bulk_g2s_ef(dst + A_BYTES, gH + (size_t)t * (SPB*H_PER), hb, barBase + s*16, pol);
                if (++s == NSTAGE) { s = 0; ph ^= 1; }
            }
        }
    } else {
        // ---------------- consumer warps 0-2: one sample per lane ----------------
        const Params p = load_params(gW, gFw, gFb);
        int s = 0; uint32_t ph = 0;
        for (int t = blockIdx.x; t < nt; t += stride) {
            const int n = min(SPB, B - t * SPB);
            mbar_wait(barBase + s*16, ph);
            if (tid < n) {
                const float* base = reinterpret_cast<const float*>(smem + s * STAGE_BYTES);
                const float* a = base + tid * A_PER;             // stride 81 (odd) -> conflict-free
                const float* h = base + SPB*A_PER + tid * H_PER; // stride 45 (odd) -> conflict-free
                out[(size_t)t * SPB + tid] = gcn_sample(a, h, p);
            }
            mbar_arrive(barBase + s*16 + 8);                     // all 96 lanes always arrive
            if (++s == NSTAGE) { s = 0; ph ^= 1; }
        }
    }
}

extern "C" void kernel_launch(void* const* d_in, const int* in_sizes, int n_in,
                              void* d_out, int out_size)
{
    const float* A   = (const float*)d_in[0];
    const float* h0  = (const float*)d_in[1];
    const float* W   = (const float*)d_in[2];
    const float* fcw = (const float*)d_in[3];
    const float* fcb = (const float*)d_in[4];
    float* out = (float*)d_out;

    cudaFuncSetAttribute(gcn_kernel, cudaFuncAttributeMaxDynamicSharedMemorySize, SMEM_BYTES);

    const int B = in_sizes[0] / A_PER;    // 1,000,000
    const int grid = 148 * 2;             // 2 blocks/SM, grid-strided tiles
    gcn_kernel<<<grid, TPB, SMEM_BYTES>>>(A, h0, W, fcw, fcb, out, B);
}